// round 2
// baseline (speedup 1.0000x reference)
#include <cuda_runtime.h>
#include <cstdint>

#define NP 200000
#define NA 100000
#define EE 1000000
#define DP 128
#define DA 64
#define HH 32

// ---------------- device scratch (no runtime allocation) ----------------
__device__ int g_deg[2 * NP + NA];   // [cites dst(NP)][writes dst(NP)][rev dst(NA)]
__device__ int g_cur[2 * NP + NA];
__device__ int g_rp [2 * NP + NA];   // segment starts (unordered CSR)
__device__ int g_cnt[3];
__device__ int g_col[3 * EE];

__device__ __align__(16) float g_P[(size_t)NP * 96]; // cols 0-31: x@W1l_c | 32-63: x@W1l_rev | 64-95: x@(W1r_c+W1r_w)
__device__ __align__(16) float g_A[(size_t)NA * 64]; // cols 0-31: x@W1l_w | 32-63: x@W1r_rev
__device__ float g_zc[NP], g_zr[NP], g_zw[NA];
__device__ __align__(16) float g_WpT[96 * 128];      // [col][k]
__device__ __align__(16) float g_WaT[64 * 64];
__device__ float g_b1[HH], g_brev[HH], g_uc[HH], g_uw[HH], g_wr2[HH];
__device__ float g_cbias;

// ---------------- helpers ----------------
__device__ __forceinline__ unsigned long long pack2(float x, float y) {
    unsigned long long r;
    asm("mov.b64 %0, {%1,%2};" : "=l"(r) : "r"(__float_as_uint(x)), "r"(__float_as_uint(y)));
    return r;
}
__device__ __forceinline__ float hsum2(unsigned long long v) {
    unsigned int lo, hi;
    asm("mov.b64 {%0,%1}, %2;" : "=r"(lo), "=r"(hi) : "l"(v));
    return __uint_as_float(lo) + __uint_as_float(hi);
}
__device__ __forceinline__ void ffma2(unsigned long long& acc,
                                      unsigned long long a, unsigned long long b) {
    asm("fma.rn.f32x2 %0, %1, %2, %0;" : "+l"(acc) : "l"(a), "l"(b));
}

// ---------------- init / weight prep ----------------
__global__ void k_zero() {
    int i = blockIdx.x * blockDim.x + threadIdx.x;
    if (i < 2 * NP + NA) { g_deg[i] = 0; g_cur[i] = 0; }
    if (i < 3) g_cnt[i] = 0;
}

__global__ void k_prep(const float* __restrict__ W1l_c,  const float* __restrict__ b1l_c,
                       const float* __restrict__ W1r_c,  const float* __restrict__ W1l_w,
                       const float* __restrict__ b1l_w,  const float* __restrict__ W1r_w,
                       const float* __restrict__ W1l_rev,const float* __restrict__ b1l_rev,
                       const float* __restrict__ W1r_rev,const float* __restrict__ W2l_c,
                       const float* __restrict__ b2l_c,  const float* __restrict__ W2r_c,
                       const float* __restrict__ W2l_w,  const float* __restrict__ b2l_w,
                       const float* __restrict__ W2r_w,  const float* __restrict__ Wh,
                       const float* __restrict__ bh) {
    int idx = blockIdx.x * blockDim.x + threadIdx.x;
    int stride = gridDim.x * blockDim.x;
    // paper combined WT: [96][128]
    for (int q = idx; q < 96 * 128; q += stride) {
        int c = q >> 7, k = q & 127;
        float v;
        if (c < 32)       v = W1l_c[k * HH + c];
        else if (c < 64)  v = W1l_rev[k * HH + (c - 32)];
        else              v = W1r_c[k * HH + (c - 64)] + W1r_w[k * HH + (c - 64)];
        g_WpT[q] = v;
    }
    // author combined WT: [64][64]
    for (int q = idx; q < 64 * 64; q += stride) {
        int c = q >> 6, k = q & 63;
        g_WaT[q] = (c < 32) ? W1l_w[k * HH + c] : W1r_rev[k * HH + (c - 32)];
    }
    if (idx < HH) {
        g_b1[idx]   = b1l_c[idx] + b1l_w[idx];
        g_brev[idx] = b1l_rev[idx];
        float uc = 0.f, uw = 0.f, wr = 0.f;
        for (int j = 0; j < HH; ++j) {
            float wh = Wh[j];
            uc += W2l_c[idx * HH + j] * wh;
            uw += W2l_w[idx * HH + j] * wh;
            wr += (W2r_c[idx * HH + j] + W2r_w[idx * HH + j]) * wh;
        }
        g_uc[idx] = uc; g_uw[idx] = uw; g_wr2[idx] = wr;
    }
    if (idx == 0) {
        float cb = bh[0];
        for (int j = 0; j < HH; ++j) cb += (b2l_c[j] + b2l_w[j]) * Wh[j];
        g_cbias = cb;
    }
}

// ---------------- CSR build ----------------
__global__ void k_hist(const int* __restrict__ dst, int off) {
    int e = blockIdx.x * blockDim.x + threadIdx.x;
    if (e < EE) atomicAdd(&g_deg[off + dst[e]], 1);
}

// scan-free segment allocation: block scan + one atomic per block (unordered CSR)
__global__ void k_alloc(int off, int n, int cidx) {
    __shared__ int sm[256];
    __shared__ int sbase;
    int t = threadIdx.x;
    int idx0 = blockIdx.x * 1024 + t * 4;
    int d0 = (idx0 + 0 < n) ? g_deg[off + idx0 + 0] : 0;
    int d1 = (idx0 + 1 < n) ? g_deg[off + idx0 + 1] : 0;
    int d2 = (idx0 + 2 < n) ? g_deg[off + idx0 + 2] : 0;
    int d3 = (idx0 + 3 < n) ? g_deg[off + idx0 + 3] : 0;
    int s = d0 + d1 + d2 + d3;
    sm[t] = s;
    __syncthreads();
    for (int o = 1; o < 256; o <<= 1) {
        int v = (t >= o) ? sm[t - o] : 0;
        __syncthreads();
        sm[t] += v;
        __syncthreads();
    }
    if (t == 255) sbase = atomicAdd(&g_cnt[cidx], sm[255]);
    __syncthreads();
    int start = sbase + sm[t] - s;
    if (idx0 + 0 < n) { g_rp[off + idx0 + 0] = start; start += d0; }
    if (idx0 + 1 < n) { g_rp[off + idx0 + 1] = start; start += d1; }
    if (idx0 + 2 < n) { g_rp[off + idx0 + 2] = start; start += d2; }
    if (idx0 + 3 < n) { g_rp[off + idx0 + 3] = start; }
}

__global__ void k_fill(const int* __restrict__ src, const int* __restrict__ dst,
                       int off, int colOff) {
    int e = blockIdx.x * blockDim.x + threadIdx.x;
    if (e >= EE) return;
    int d = dst[e];
    int p = g_rp[off + d] + atomicAdd(&g_cur[off + d], 1);
    g_col[colOff + p] = src[e];
}

// ---------------- projection GEMM: C[M,N] = A[M,K] @ WT^T, f32x2 path ----------------
// BM=128, BK=32, 256 threads. Thread (rg=tid&15, cg=tid>>4) owns rows rg+16r (r<8),
// cols cg*CPT..cg*CPT+CPT-1. A tile K-major in smem (conflict-free), W half-warp broadcast.
template <int K, int N>
__device__ __forceinline__ void gemm_body(const float* __restrict__ A,
                                          const float* __restrict__ WT,
                                          float* __restrict__ C, int M) {
    constexpr int BK  = 32;
    constexpr int KP  = BK / 2;       // 16 k-pairs per tile
    constexpr int CPT = N / 16;       // cols per thread (6 or 4)
    __shared__ unsigned long long As[KP * 128];       // [kpair][row], 16KB
    __shared__ unsigned long long Ws[N * (KP + 1)];   // [col][kpair], padded

    const int tid = threadIdx.x;
    const int rg = tid & 15;
    const int cg = tid >> 4;
    const int row0 = blockIdx.x * 128;

    unsigned long long acc[8][CPT];
#pragma unroll
    for (int r = 0; r < 8; ++r)
#pragma unroll
        for (int c = 0; c < CPT; ++c) acc[r][c] = 0ull;

#pragma unroll 1
    for (int kb = 0; kb < K; kb += BK) {
        __syncthreads();
        // A tile: 128 rows x 32 k = 1024 float4 / 256 threads
#pragma unroll
        for (int i = 0; i < 4; ++i) {
            int q = tid + i * 256;
            int r = q & 127, f4 = q >> 7;
            int gr = row0 + r;
            if (gr > M - 1) gr = M - 1;
            float4 v = *(const float4*)(A + (size_t)gr * K + kb + f4 * 4);
            As[(f4 * 2 + 0) * 128 + r] = pack2(v.x, v.y);
            As[(f4 * 2 + 1) * 128 + r] = pack2(v.z, v.w);
        }
        // W tile: N x 16 pairs
        for (int q = tid; q < N * KP; q += 256) {
            int c = q / KP, kp = q % KP;
            Ws[c * (KP + 1) + kp] = *(const unsigned long long*)(WT + c * K + kb + kp * 2);
        }
        __syncthreads();
#pragma unroll
        for (int kp = 0; kp < KP; ++kp) {
            unsigned long long a2[8], w2[CPT];
#pragma unroll
            for (int r = 0; r < 8; ++r) a2[r] = As[kp * 128 + rg + 16 * r];
#pragma unroll
            for (int c = 0; c < CPT; ++c) w2[c] = Ws[(cg * CPT + c) * (KP + 1) + kp];
#pragma unroll
            for (int r = 0; r < 8; ++r)
#pragma unroll
                for (int c = 0; c < CPT; ++c) ffma2(acc[r][c], a2[r], w2[c]);
        }
    }

    // epilogue via smem (alias As, 4096 floats) for coalesced float4 stores
    float* Cs = reinterpret_cast<float*>(As);
    constexpr int RPC = ((4096 / N) / 16) * 16;   // rows per chunk: 32 (N=96) / 64 (N=64)
    constexpr int RPT = RPC / 16;
    constexpr int NCH = 128 / RPC;
#pragma unroll
    for (int ch = 0; ch < NCH; ++ch) {
        __syncthreads();
#pragma unroll
        for (int rr = 0; rr < RPT; ++rr) {
            int r = ch * RPT + rr;
            int lr = rg + 16 * rr;
#pragma unroll
            for (int c = 0; c < CPT; ++c)
                Cs[lr * N + cg * CPT + c] = hsum2(acc[r][c]);
        }
        __syncthreads();
        for (int q = tid; q < RPC * N / 4; q += 256) {
            int lr = q / (N / 4), f = q % (N / 4);
            int grow = row0 + ch * RPC + lr;
            if (grow < M)
                *(float4*)(C + (size_t)grow * N + f * 4) = *(const float4*)(Cs + lr * N + f * 4);
        }
    }
}

__global__ void __launch_bounds__(256) k_gemm_paper(const float* __restrict__ A) {
    gemm_body<128, 96>(A, g_WpT, g_P, NP);
}
__global__ void __launch_bounds__(256) k_gemm_author(const float* __restrict__ A) {
    gemm_body<64, 64>(A, g_WaT, g_A, NA);
}

// ---------------- layer-1 gathers fused with layer-2 scalar projections ----------------
__global__ void k_paper() {
    int w = (blockIdx.x << 3) + (threadIdx.x >> 5);
    if (w >= NP) return;
    int lane = threadIdx.x & 31;

    int s = g_rp[w], d = g_deg[w];
    float ac = 0.f;
    for (int e = 0; e < d; ++e) {
        int src = g_col[s + e];
        ac += g_P[(size_t)src * 96 + lane];
    }
    int s2 = g_rp[NP + w], d2 = g_deg[NP + w];
    float aw = 0.f;
    for (int e = 0; e < d2; ++e) {
        int src = g_col[EE + s2 + e];
        aw += g_A[(size_t)src * 64 + lane];
    }
    float p = ac / fmaxf((float)d, 1.f) + aw / fmaxf((float)d2, 1.f)
            + g_P[(size_t)w * 96 + 64 + lane] + g_b1[lane];
    p = fmaxf(p, 0.f);
    float zc = p * g_uc[lane];
    float zr = p * g_wr2[lane];
#pragma unroll
    for (int o = 16; o; o >>= 1) {
        zc += __shfl_xor_sync(0xFFFFFFFFu, zc, o);
        zr += __shfl_xor_sync(0xFFFFFFFFu, zr, o);
    }
    if (lane == 0) { g_zc[w] = zc; g_zr[w] = zr; }
}

__global__ void k_author() {
    int w = (blockIdx.x << 3) + (threadIdx.x >> 5);
    if (w >= NA) return;
    int lane = threadIdx.x & 31;

    int s = g_rp[2 * NP + w], d = g_deg[2 * NP + w];
    float ar = 0.f;
    for (int e = 0; e < d; ++e) {
        int src = g_col[2 * EE + s + e];
        ar += g_P[(size_t)src * 96 + 32 + lane];
    }
    float a1 = ar / fmaxf((float)d, 1.f) + g_A[(size_t)w * 64 + 32 + lane] + g_brev[lane];
    a1 = fmaxf(a1, 0.f);
    float zw = a1 * g_uw[lane];
#pragma unroll
    for (int o = 16; o; o >>= 1) zw += __shfl_xor_sync(0xFFFFFFFFu, zw, o);
    if (lane == 0) g_zw[w] = zw;
}

// ---------------- layer 2 scalar aggregation + head ----------------
__global__ void k_out(float* __restrict__ out) {
    int i = blockIdx.x * blockDim.x + threadIdx.x;
    if (i >= NP) return;
    int s = g_rp[i], d = g_deg[i];
    float sc = 0.f;
    for (int e = 0; e < d; ++e) sc += g_zc[g_col[s + e]];
    int s2 = g_rp[NP + i], d2 = g_deg[NP + i];
    float sw = 0.f;
    for (int e = 0; e < d2; ++e) sw += g_zw[g_col[EE + s2 + e]];
    out[i] = sc / fmaxf((float)d, 1.f) + sw / fmaxf((float)d2, 1.f) + g_zr[i] + g_cbias;
}

// ---------------- launch ----------------
extern "C" void kernel_launch(void* const* d_in, const int* in_sizes, int n_in,
                              void* d_out, int out_size) {
    const float* x_paper  = (const float*)d_in[0];
    const float* x_author = (const float*)d_in[1];
    const int*   ei_c     = (const int*)d_in[2];
    const int*   ei_w     = (const int*)d_in[3];
    const int*   ei_r     = (const int*)d_in[4];
    float* out = (float*)d_out;

    k_zero<<<(2 * NP + NA + 255) / 256, 256>>>();
    k_prep<<<48, 256>>>((const float*)d_in[5],  (const float*)d_in[6],  (const float*)d_in[7],
                        (const float*)d_in[8],  (const float*)d_in[9],  (const float*)d_in[10],
                        (const float*)d_in[11], (const float*)d_in[12], (const float*)d_in[13],
                        (const float*)d_in[14], (const float*)d_in[15], (const float*)d_in[16],
                        (const float*)d_in[17], (const float*)d_in[18], (const float*)d_in[19],
                        (const float*)d_in[23], (const float*)d_in[24]);

    const int EB = (EE + 255) / 256;
    k_hist<<<EB, 256>>>(ei_c + EE, 0);
    k_hist<<<EB, 256>>>(ei_w + EE, NP);
    k_hist<<<EB, 256>>>(ei_r + EE, 2 * NP);

    k_alloc<<<(NP + 1023) / 1024, 256>>>(0, NP, 0);
    k_alloc<<<(NP + 1023) / 1024, 256>>>(NP, NP, 1);
    k_alloc<<<(NA + 1023) / 1024, 256>>>(2 * NP, NA, 2);

    k_fill<<<EB, 256>>>(ei_c, ei_c + EE, 0, 0);
    k_fill<<<EB, 256>>>(ei_w, ei_w + EE, NP, EE);
    k_fill<<<EB, 256>>>(ei_r, ei_r + EE, 2 * NP, 2 * EE);

    k_gemm_paper<<<(NP + 127) / 128, 256>>>(x_paper);
    k_gemm_author<<<(NA + 127) / 128, 256>>>(x_author);

    k_paper<<<(NP + 7) / 8, 256>>>();
    k_author<<<(NA + 7) / 8, 256>>>();
    k_out<<<(NP + 255) / 256, 256>>>(out);
}

// round 3
// speedup vs baseline: 1.0522x; 1.0522x over previous
#include <cuda_runtime.h>
#include <cstdint>

#define NP 200000
#define NA 100000
#define EE 1000000
#define DP 128
#define DA 64
#define HH 32

// ---------------- device scratch (no runtime allocation) ----------------
__device__ int g_deg[2 * NP + NA];   // [cites dst(NP)][writes dst(NP)][rev dst(NA)]
__device__ int g_cur[2 * NP + NA];   // fill cursor, initialized to rp by k_alloc3
__device__ int g_rp [2 * NP + NA];   // segment starts (unordered CSR)
__device__ int g_cnt[3];
__device__ int g_col[3 * EE];

__device__ __align__(16) float g_P[(size_t)NP * 96]; // 0-31: x@W1l_c | 32-63: x@W1l_rev | 64-95: x@(W1r_c+W1r_w)
__device__ __align__(16) float g_A[(size_t)NA * 64]; // 0-31: x@W1l_w | 32-63: x@W1r_rev
__device__ float g_zc[NP], g_zr[NP], g_zw[NA];
__device__ __align__(16) float g_WpT[96 * 128];      // [col][k]
__device__ __align__(16) float g_WaT[64 * 64];
__device__ float g_b1[HH], g_brev[HH], g_uc[HH], g_uw[HH], g_wr2[HH];
__device__ float g_cbias;

// ---------------- helpers ----------------
__device__ __forceinline__ unsigned long long pack2(float x, float y) {
    unsigned long long r;
    asm("mov.b64 %0, {%1,%2};" : "=l"(r) : "r"(__float_as_uint(x)), "r"(__float_as_uint(y)));
    return r;
}
__device__ __forceinline__ float hsum2(unsigned long long v) {
    unsigned int lo, hi;
    asm("mov.b64 {%0,%1}, %2;" : "=r"(lo), "=r"(hi) : "l"(v));
    return __uint_as_float(lo) + __uint_as_float(hi);
}
__device__ __forceinline__ void ffma2(unsigned long long& acc,
                                      unsigned long long a, unsigned long long b) {
    asm("fma.rn.f32x2 %0, %1, %2, %0;" : "+l"(acc) : "l"(a), "l"(b));
}

// ---------------- init / weight prep ----------------
__global__ void k_zero() {
    int i = blockIdx.x * blockDim.x + threadIdx.x;
    if (i < 2 * NP + NA) g_deg[i] = 0;
    if (i < 3) g_cnt[i] = 0;
}

__global__ void k_prep(const float* __restrict__ W1l_c,  const float* __restrict__ b1l_c,
                       const float* __restrict__ W1r_c,  const float* __restrict__ W1l_w,
                       const float* __restrict__ b1l_w,  const float* __restrict__ W1r_w,
                       const float* __restrict__ W1l_rev,const float* __restrict__ b1l_rev,
                       const float* __restrict__ W1r_rev,const float* __restrict__ W2l_c,
                       const float* __restrict__ b2l_c,  const float* __restrict__ W2r_c,
                       const float* __restrict__ W2l_w,  const float* __restrict__ b2l_w,
                       const float* __restrict__ W2r_w,  const float* __restrict__ Wh,
                       const float* __restrict__ bh) {
    int idx = blockIdx.x * blockDim.x + threadIdx.x;
    int stride = gridDim.x * blockDim.x;
    for (int q = idx; q < 96 * 128; q += stride) {
        int c = q >> 7, k = q & 127;
        float v;
        if (c < 32)       v = W1l_c[k * HH + c];
        else if (c < 64)  v = W1l_rev[k * HH + (c - 32)];
        else              v = W1r_c[k * HH + (c - 64)] + W1r_w[k * HH + (c - 64)];
        g_WpT[q] = v;
    }
    for (int q = idx; q < 64 * 64; q += stride) {
        int c = q >> 6, k = q & 63;
        g_WaT[q] = (c < 32) ? W1l_w[k * HH + c] : W1r_rev[k * HH + (c - 32)];
    }
    if (idx < HH) {
        g_b1[idx]   = b1l_c[idx] + b1l_w[idx];
        g_brev[idx] = b1l_rev[idx];
        float uc = 0.f, uw = 0.f, wr = 0.f;
        for (int j = 0; j < HH; ++j) {
            float wh = Wh[j];
            uc += W2l_c[idx * HH + j] * wh;
            uw += W2l_w[idx * HH + j] * wh;
            wr += (W2r_c[idx * HH + j] + W2r_w[idx * HH + j]) * wh;
        }
        g_uc[idx] = uc; g_uw[idx] = uw; g_wr2[idx] = wr;
    }
    if (idx == 0) {
        float cb = bh[0];
        for (int j = 0; j < HH; ++j) cb += (b2l_c[j] + b2l_w[j]) * Wh[j];
        g_cbias = cb;
    }
}

// ---------------- CSR build (merged kernels) ----------------
__global__ void k_hist3(const int* __restrict__ dc, const int* __restrict__ dw,
                        const int* __restrict__ dr) {
    int e = blockIdx.x * blockDim.x + threadIdx.x;
    if (e < EE)            atomicAdd(&g_deg[__ldg(dc + e)], 1);
    else if (e < 2 * EE)   atomicAdd(&g_deg[NP + __ldg(dw + e - EE)], 1);
    else if (e < 3 * EE)   atomicAdd(&g_deg[2 * NP + __ldg(dr + e - 2 * EE)], 1);
}

// scan-free segment allocation: block scan + one atomic per block (unordered CSR)
// writes segment start to BOTH g_rp (kept) and g_cur (consumed by fill)
__global__ void k_alloc3() {
    __shared__ int sm[256];
    __shared__ int sbase;
    int b = blockIdx.x;
    int off, n, cidx, lb;
    if (b < 196)      { off = 0;      n = NP; cidx = 0; lb = b; }
    else if (b < 392) { off = NP;     n = NP; cidx = 1; lb = b - 196; }
    else              { off = 2 * NP; n = NA; cidx = 2; lb = b - 392; }

    int t = threadIdx.x;
    int idx0 = lb * 1024 + t * 4;
    int d0 = (idx0 + 0 < n) ? g_deg[off + idx0 + 0] : 0;
    int d1 = (idx0 + 1 < n) ? g_deg[off + idx0 + 1] : 0;
    int d2 = (idx0 + 2 < n) ? g_deg[off + idx0 + 2] : 0;
    int d3 = (idx0 + 3 < n) ? g_deg[off + idx0 + 3] : 0;
    int s = d0 + d1 + d2 + d3;
    sm[t] = s;
    __syncthreads();
    for (int o = 1; o < 256; o <<= 1) {
        int v = (t >= o) ? sm[t - o] : 0;
        __syncthreads();
        sm[t] += v;
        __syncthreads();
    }
    if (t == 255) sbase = atomicAdd(&g_cnt[cidx], sm[255]);
    __syncthreads();
    int start = sbase + sm[t] - s;
    if (idx0 + 0 < n) { g_rp[off + idx0 + 0] = start; g_cur[off + idx0 + 0] = start; start += d0; }
    if (idx0 + 1 < n) { g_rp[off + idx0 + 1] = start; g_cur[off + idx0 + 1] = start; start += d1; }
    if (idx0 + 2 < n) { g_rp[off + idx0 + 2] = start; g_cur[off + idx0 + 2] = start; start += d2; }
    if (idx0 + 3 < n) { g_rp[off + idx0 + 3] = start; g_cur[off + idx0 + 3] = start; }
}

__global__ void k_fill3(const int* __restrict__ sc, const int* __restrict__ dc,
                        const int* __restrict__ sw, const int* __restrict__ dw,
                        const int* __restrict__ sr, const int* __restrict__ dr) {
    int e = blockIdx.x * blockDim.x + threadIdx.x;
    const int* s; const int* d; int off, colOff, le;
    if (e < EE)          { s = sc; d = dc; off = 0;      colOff = 0;      le = e; }
    else if (e < 2 * EE) { s = sw; d = dw; off = NP;     colOff = EE;     le = e - EE; }
    else if (e < 3 * EE) { s = sr; d = dr; off = 2 * NP; colOff = 2 * EE; le = e - 2 * EE; }
    else return;
    int dd = __ldg(d + le);
    int p = atomicAdd(&g_cur[off + dd], 1);
    g_col[colOff + p] = __ldg(s + le);
}

// ---------------- projection GEMM: C[M,N] = A[M,K] @ WT^T, f32x2 path ----------------
template <int K, int N>
__device__ __forceinline__ void gemm_body(const float* __restrict__ A,
                                          const float* __restrict__ WT,
                                          float* __restrict__ C, int M) {
    constexpr int BK  = 32;
    constexpr int KP  = BK / 2;
    constexpr int CPT = N / 16;
    __shared__ unsigned long long As[KP * 128];
    __shared__ unsigned long long Ws[N * (KP + 1)];

    const int tid = threadIdx.x;
    const int rg = tid & 15;
    const int cg = tid >> 4;
    const int row0 = blockIdx.x * 128;

    unsigned long long acc[8][CPT];
#pragma unroll
    for (int r = 0; r < 8; ++r)
#pragma unroll
        for (int c = 0; c < CPT; ++c) acc[r][c] = 0ull;

#pragma unroll 1
    for (int kb = 0; kb < K; kb += BK) {
        __syncthreads();
#pragma unroll
        for (int i = 0; i < 4; ++i) {
            int q = tid + i * 256;
            int r = q & 127, f4 = q >> 7;
            int gr = row0 + r;
            if (gr > M - 1) gr = M - 1;
            float4 v = *(const float4*)(A + (size_t)gr * K + kb + f4 * 4);
            As[(f4 * 2 + 0) * 128 + r] = pack2(v.x, v.y);
            As[(f4 * 2 + 1) * 128 + r] = pack2(v.z, v.w);
        }
        for (int q = tid; q < N * KP; q += 256) {
            int c = q / KP, kp = q % KP;
            Ws[c * (KP + 1) + kp] = *(const unsigned long long*)(WT + c * K + kb + kp * 2);
        }
        __syncthreads();
#pragma unroll
        for (int kp = 0; kp < KP; ++kp) {
            unsigned long long a2[8], w2[CPT];
#pragma unroll
            for (int r = 0; r < 8; ++r) a2[r] = As[kp * 128 + rg + 16 * r];
#pragma unroll
            for (int c = 0; c < CPT; ++c) w2[c] = Ws[(cg * CPT + c) * (KP + 1) + kp];
#pragma unroll
            for (int r = 0; r < 8; ++r)
#pragma unroll
                for (int c = 0; c < CPT; ++c) ffma2(acc[r][c], a2[r], w2[c]);
        }
    }

    float* Cs = reinterpret_cast<float*>(As);
    constexpr int RPC = ((4096 / N) / 16) * 16;
    constexpr int RPT = RPC / 16;
    constexpr int NCH = 128 / RPC;
#pragma unroll
    for (int ch = 0; ch < NCH; ++ch) {
        __syncthreads();
#pragma unroll
        for (int rr = 0; rr < RPT; ++rr) {
            int r = ch * RPT + rr;
            int lr = rg + 16 * rr;
#pragma unroll
            for (int c = 0; c < CPT; ++c)
                Cs[lr * N + cg * CPT + c] = hsum2(acc[r][c]);
        }
        __syncthreads();
        for (int q = tid; q < RPC * N / 4; q += 256) {
            int lr = q / (N / 4), f = q % (N / 4);
            int grow = row0 + ch * RPC + lr;
            if (grow < M)
                *(float4*)(C + (size_t)grow * N + f * 4) = *(const float4*)(Cs + lr * N + f * 4);
        }
    }
}

__global__ void __launch_bounds__(256) k_gemm_paper(const float* __restrict__ A) {
    gemm_body<128, 96>(A, g_WpT, g_P, NP);
}
__global__ void __launch_bounds__(256) k_gemm_author(const float* __restrict__ A) {
    gemm_body<64, 64>(A, g_WaT, g_A, NA);
}

// ---------------- layer-1 gathers (MLP=4) fused with layer-2 scalar projections ----------------
__device__ __forceinline__ float gather_mean32(const int* __restrict__ col, int d,
                                               const float* __restrict__ base, int stride,
                                               int lane) {
    float acc = 0.f;
    for (int e = 0; e < d; e += 4) {
        int i0 = __ldg(col + e);
        int i1 = 0, i2 = 0, i3 = 0;
        if (e + 1 < d) i1 = __ldg(col + e + 1);
        if (e + 2 < d) i2 = __ldg(col + e + 2);
        if (e + 3 < d) i3 = __ldg(col + e + 3);
        float v0 = __ldg(base + i0 * stride + lane);
        float v1 = 0.f, v2 = 0.f, v3 = 0.f;
        if (e + 1 < d) v1 = __ldg(base + i1 * stride + lane);
        if (e + 2 < d) v2 = __ldg(base + i2 * stride + lane);
        if (e + 3 < d) v3 = __ldg(base + i3 * stride + lane);
        acc += (v0 + v1) + (v2 + v3);
    }
    return acc / fmaxf((float)d, 1.f);
}

__global__ void __launch_bounds__(256) k_paper() {
    int w = blockIdx.x * 8 + (threadIdx.x >> 5);
    if (w >= NP) return;
    int lane = threadIdx.x & 31;

    int s  = __ldg(&g_rp[w]);      int d  = __ldg(&g_deg[w]);
    int s2 = __ldg(&g_rp[NP + w]); int d2 = __ldg(&g_deg[NP + w]);

    float mc = gather_mean32(g_col + s, d, g_P, 96, lane);
    float mw = gather_mean32(g_col + EE + s2, d2, g_A, 64, lane);

    float p = mc + mw + __ldg(g_P + w * 96 + 64 + lane) + g_b1[lane];
    p = fmaxf(p, 0.f);
    float zc = p * g_uc[lane];
    float zr = p * g_wr2[lane];
#pragma unroll
    for (int o = 16; o; o >>= 1) {
        zc += __shfl_xor_sync(0xFFFFFFFFu, zc, o);
        zr += __shfl_xor_sync(0xFFFFFFFFu, zr, o);
    }
    if (lane == 0) { g_zc[w] = zc; g_zr[w] = zr; }
}

__global__ void __launch_bounds__(256) k_author() {
    int w = blockIdx.x * 8 + (threadIdx.x >> 5);
    if (w >= NA) return;
    int lane = threadIdx.x & 31;

    int s = __ldg(&g_rp[2 * NP + w]); int d = __ldg(&g_deg[2 * NP + w]);
    float mr = gather_mean32(g_col + 2 * EE + s, d, g_P + 32, 96, lane);

    float a1 = mr + __ldg(g_A + w * 64 + 32 + lane) + g_brev[lane];
    a1 = fmaxf(a1, 0.f);
    float zw = a1 * g_uw[lane];
#pragma unroll
    for (int o = 16; o; o >>= 1) zw += __shfl_xor_sync(0xFFFFFFFFu, zw, o);
    if (lane == 0) g_zw[w] = zw;
}

// ---------------- layer 2 scalar aggregation + head (MLP=4) ----------------
__device__ __forceinline__ float gather_mean1(const int* __restrict__ col, int d,
                                              const float* __restrict__ z) {
    float acc = 0.f;
    for (int e = 0; e < d; e += 4) {
        int i0 = __ldg(col + e);
        int i1 = 0, i2 = 0, i3 = 0;
        if (e + 1 < d) i1 = __ldg(col + e + 1);
        if (e + 2 < d) i2 = __ldg(col + e + 2);
        if (e + 3 < d) i3 = __ldg(col + e + 3);
        float v0 = __ldg(z + i0);
        float v1 = 0.f, v2 = 0.f, v3 = 0.f;
        if (e + 1 < d) v1 = __ldg(z + i1);
        if (e + 2 < d) v2 = __ldg(z + i2);
        if (e + 3 < d) v3 = __ldg(z + i3);
        acc += (v0 + v1) + (v2 + v3);
    }
    return acc / fmaxf((float)d, 1.f);
}

__global__ void __launch_bounds__(256) k_out(float* __restrict__ out) {
    int i = blockIdx.x * blockDim.x + threadIdx.x;
    if (i >= NP) return;
    int s  = __ldg(&g_rp[i]);      int d  = __ldg(&g_deg[i]);
    int s2 = __ldg(&g_rp[NP + i]); int d2 = __ldg(&g_deg[NP + i]);
    float sc = gather_mean1(g_col + s, d, g_zc);
    float sw = gather_mean1(g_col + EE + s2, d2, g_zw);
    out[i] = sc + sw + __ldg(&g_zr[i]) + g_cbias;
}

// ---------------- launch ----------------
extern "C" void kernel_launch(void* const* d_in, const int* in_sizes, int n_in,
                              void* d_out, int out_size) {
    const float* x_paper  = (const float*)d_in[0];
    const float* x_author = (const float*)d_in[1];
    const int*   ei_c     = (const int*)d_in[2];
    const int*   ei_w     = (const int*)d_in[3];
    const int*   ei_r     = (const int*)d_in[4];
    float* out = (float*)d_out;

    k_zero<<<(2 * NP + NA + 255) / 256, 256>>>();
    k_prep<<<48, 256>>>((const float*)d_in[5],  (const float*)d_in[6],  (const float*)d_in[7],
                        (const float*)d_in[8],  (const float*)d_in[9],  (const float*)d_in[10],
                        (const float*)d_in[11], (const float*)d_in[12], (const float*)d_in[13],
                        (const float*)d_in[14], (const float*)d_in[15], (const float*)d_in[16],
                        (const float*)d_in[17], (const float*)d_in[18], (const float*)d_in[19],
                        (const float*)d_in[23], (const float*)d_in[24]);

    k_hist3<<<(3 * EE + 255) / 256, 256>>>(ei_c + EE, ei_w + EE, ei_r + EE);
    k_alloc3<<<490, 256>>>();
    k_fill3<<<(3 * EE + 255) / 256, 256>>>(ei_c, ei_c + EE, ei_w, ei_w + EE, ei_r, ei_r + EE);

    k_gemm_paper<<<(NP + 127) / 128, 256>>>(x_paper);
    k_gemm_author<<<(NA + 127) / 128, 256>>>(x_author);

    k_paper<<<(NP + 7) / 8, 256>>>();
    k_author<<<(NA + 7) / 8, 256>>>();
    k_out<<<(NP + 255) / 256, 256>>>(out);
}

// round 7
// speedup vs baseline: 1.5711x; 1.4931x over previous
#include <cuda_runtime.h>
#include <cuda_bf16.h>
#include <cstdint>

#define NP 200000
#define NA 100000
#define EE 1000000
#define HH 32

// ---------------- device scratch (no runtime allocation) ----------------
__device__ int g_deg[2 * NP + NA];
__device__ int g_cur[2 * NP + NA];
__device__ int g_rp [2 * NP + NA];
__device__ int g_cnt[3];
__device__ int g_col[3 * EE];

__device__ __align__(16) float g_P[(size_t)NP * 96]; // 0-31: x@W1l_c | 32-63: x@W1l_rev | 64-95: x@(W1r_c+W1r_w)
__device__ __align__(16) float g_A[(size_t)NA * 64]; // 0-31: x@W1l_w | 32-63: x@W1r_rev
__device__ float g_zc[NP], g_zr[NP], g_zw[NA];

// bf16 split B images, row-major [N][2K]: cols 0..K-1 = hi(W), cols K..2K-1 = lo(W)
__device__ __align__(16) __nv_bfloat16 g_WbP[96 * 256];
__device__ __align__(16) __nv_bfloat16 g_WbA[64 * 128];
__device__ float g_b1[HH], g_brev[HH], g_uc[HH], g_uw[HH], g_wr2[HH];
__device__ float g_cbias;

// ---------------- helpers ----------------
__device__ __forceinline__ uint32_t smem_u32(const void* p) {
    uint32_t a;
    asm("{ .reg .u64 t; cvta.to.shared.u64 t, %1; cvt.u32.u64 %0, t; }" : "=r"(a) : "l"(p));
    return a;
}
__device__ __forceinline__ unsigned int pack_bf16(float a, float b) {
    __nv_bfloat162 h = __floats2bfloat162_rn(a, b);
    return *reinterpret_cast<unsigned int*>(&h);
}
__device__ __forceinline__ void ldsm4(uint32_t& r0, uint32_t& r1, uint32_t& r2, uint32_t& r3,
                                      uint32_t addr) {
    asm volatile("ldmatrix.sync.aligned.m8n8.x4.shared.b16 {%0,%1,%2,%3}, [%4];"
                 : "=r"(r0), "=r"(r1), "=r"(r2), "=r"(r3) : "r"(addr));
}
__device__ __forceinline__ void mma16816(float* d, const uint32_t* a, uint32_t b0, uint32_t b1) {
    asm volatile(
        "mma.sync.aligned.m16n8k16.row.col.f32.bf16.bf16.f32 "
        "{%0,%1,%2,%3}, {%4,%5,%6,%7}, {%8,%9}, {%0,%1,%2,%3};"
        : "+f"(d[0]), "+f"(d[1]), "+f"(d[2]), "+f"(d[3])
        : "r"(a[0]), "r"(a[1]), "r"(a[2]), "r"(a[3]), "r"(b0), "r"(b1));
}

// ---------------- init / weight prep ----------------
__global__ void k_zero() {
    int i = blockIdx.x * blockDim.x + threadIdx.x;
    if (i < 2 * NP + NA) g_deg[i] = 0;
    if (i < 3) g_cnt[i] = 0;
}

__global__ void k_prep(const float* __restrict__ W1l_c,  const float* __restrict__ b1l_c,
                       const float* __restrict__ W1r_c,  const float* __restrict__ W1l_w,
                       const float* __restrict__ b1l_w,  const float* __restrict__ W1r_w,
                       const float* __restrict__ W1l_rev,const float* __restrict__ b1l_rev,
                       const float* __restrict__ W1r_rev,const float* __restrict__ W2l_c,
                       const float* __restrict__ b2l_c,  const float* __restrict__ W2r_c,
                       const float* __restrict__ W2l_w,  const float* __restrict__ b2l_w,
                       const float* __restrict__ W2r_w,  const float* __restrict__ Wh,
                       const float* __restrict__ bh) {
    int idx = blockIdx.x * blockDim.x + threadIdx.x;
    int stride = gridDim.x * blockDim.x;

    // paper B image [96][256]
    for (int q = idx; q < 96 * 256; q += stride) {
        int n = q >> 8, kc = q & 255;
        int k = kc & 127;
        bool lo = kc >= 128;
        float v;
        if (n < 32)      v = W1l_c[k * HH + n];
        else if (n < 64) v = W1l_rev[k * HH + n - 32];
        else             v = W1r_c[k * HH + n - 64] + W1r_w[k * HH + n - 64];
        __nv_bfloat16 h = __float2bfloat16(v);
        g_WbP[q] = lo ? __float2bfloat16(v - __bfloat162float(h)) : h;
    }
    // author B image [64][128]
    for (int q = idx; q < 64 * 128; q += stride) {
        int n = q >> 7, kc = q & 127;
        int k = kc & 63;
        bool lo = kc >= 64;
        float v = (n < 32) ? W1l_w[k * HH + n] : W1r_rev[k * HH + n - 32];
        __nv_bfloat16 h = __float2bfloat16(v);
        g_WbA[q] = lo ? __float2bfloat16(v - __bfloat162float(h)) : h;
    }
    if (idx < HH) {
        g_b1[idx]   = b1l_c[idx] + b1l_w[idx];
        g_brev[idx] = b1l_rev[idx];
        float uc = 0.f, uw = 0.f, wr = 0.f;
        for (int j = 0; j < HH; ++j) {
            float wh = Wh[j];
            uc += W2l_c[idx * HH + j] * wh;
            uw += W2l_w[idx * HH + j] * wh;
            wr += (W2r_c[idx * HH + j] + W2r_w[idx * HH + j]) * wh;
        }
        g_uc[idx] = uc; g_uw[idx] = uw; g_wr2[idx] = wr;
    }
    if (idx == 0) {
        float cb = bh[0];
        for (int j = 0; j < HH; ++j) cb += (b2l_c[j] + b2l_w[j]) * Wh[j];
        g_cbias = cb;
    }
}

// ---------------- CSR build ----------------
__global__ void k_hist3(const int* __restrict__ dc, const int* __restrict__ dw,
                        const int* __restrict__ dr) {
    int e = blockIdx.x * blockDim.x + threadIdx.x;
    if (e < EE)            atomicAdd(&g_deg[__ldg(dc + e)], 1);
    else if (e < 2 * EE)   atomicAdd(&g_deg[NP + __ldg(dw + e - EE)], 1);
    else if (e < 3 * EE)   atomicAdd(&g_deg[2 * NP + __ldg(dr + e - 2 * EE)], 1);
}

__global__ void k_alloc3() {
    __shared__ int sm[256];
    __shared__ int sbase;
    int b = blockIdx.x;
    int off, n, cidx, lb;
    if (b < 196)      { off = 0;      n = NP; cidx = 0; lb = b; }
    else if (b < 392) { off = NP;     n = NP; cidx = 1; lb = b - 196; }
    else              { off = 2 * NP; n = NA; cidx = 2; lb = b - 392; }

    int t = threadIdx.x;
    int idx0 = lb * 1024 + t * 4;
    int d0 = (idx0 + 0 < n) ? g_deg[off + idx0 + 0] : 0;
    int d1 = (idx0 + 1 < n) ? g_deg[off + idx0 + 1] : 0;
    int d2 = (idx0 + 2 < n) ? g_deg[off + idx0 + 2] : 0;
    int d3 = (idx0 + 3 < n) ? g_deg[off + idx0 + 3] : 0;
    int s = d0 + d1 + d2 + d3;
    sm[t] = s;
    __syncthreads();
    for (int o = 1; o < 256; o <<= 1) {
        int v = (t >= o) ? sm[t - o] : 0;
        __syncthreads();
        sm[t] += v;
        __syncthreads();
    }
    if (t == 255) sbase = atomicAdd(&g_cnt[cidx], sm[255]);
    __syncthreads();
    int start = sbase + sm[t] - s;
    if (idx0 + 0 < n) { g_rp[off + idx0 + 0] = start; g_cur[off + idx0 + 0] = start; start += d0; }
    if (idx0 + 1 < n) { g_rp[off + idx0 + 1] = start; g_cur[off + idx0 + 1] = start; start += d1; }
    if (idx0 + 2 < n) { g_rp[off + idx0 + 2] = start; g_cur[off + idx0 + 2] = start; start += d2; }
    if (idx0 + 3 < n) { g_rp[off + idx0 + 3] = start; g_cur[off + idx0 + 3] = start; }
}

__global__ void k_fill3(const int* __restrict__ sc, const int* __restrict__ dc,
                        const int* __restrict__ sw, const int* __restrict__ dw,
                        const int* __restrict__ sr, const int* __restrict__ dr) {
    int e = blockIdx.x * blockDim.x + threadIdx.x;
    const int* s; const int* d; int off, colOff, le;
    if (e < EE)          { s = sc; d = dc; off = 0;      colOff = 0;      le = e; }
    else if (e < 2 * EE) { s = sw; d = dw; off = NP;     colOff = EE;     le = e - EE; }
    else if (e < 3 * EE) { s = sr; d = dr; off = 2 * NP; colOff = 2 * EE; le = e - 2 * EE; }
    else return;
    int dd = __ldg(d + le);
    int p = atomicAdd(&g_cur[off + dd], 1);
    g_col[colOff + p] = __ldg(s + le);
}

// ---------------- mma.sync bf16 3-term-split GEMM, static smem <= 48KB ----------------
// C[M,N] = A[M,K]f32 @ W[K,N] via Ah·Bh + Al·Bh + Ah·Bl (err ~1e-5).
// BM=64, K chunked by 64. All global pointers are referenced from DEVICE code only
// (passing __device__ symbols as host-side kernel args was the R5/R6 zero-output bug).
template <int K, int N>
__device__ __forceinline__ void gemm_body(const float* __restrict__ A,
                                          const __nv_bfloat16* __restrict__ B, // [N][2K]
                                          float* __restrict__ C, int M) {
    constexpr int CK  = 64;
    constexpr int NCH = K / CK;
    constexpr int STR = 2 * CK + 8;   // 136
    constexpr int NT  = N / 16;       // col 8-tiles per warp (6 or 4)
    __shared__ __nv_bfloat16 As[64 * STR];
    __shared__ __nv_bfloat16 Bs[N * STR];

    const int tid = threadIdx.x;
    const int warp = tid >> 5, lane = tid & 31;
    const int wr = warp & 3, wc = warp >> 2;
    const int lr = lane & 7, sel = lane >> 3;
    const int row0 = blockIdx.x * 64;
    const uint32_t As_u = smem_u32(As), Bs_u = smem_u32(Bs);

    float d[NT][4];
#pragma unroll
    for (int nt = 0; nt < NT; ++nt)
#pragma unroll
        for (int j = 0; j < 4; ++j) d[nt][j] = 0.f;

#pragma unroll
    for (int ch = 0; ch < NCH; ++ch) {
        __syncthreads();
        // A chunk: 64 rows x 64 f32, split hi/lo
        {
            const int q = tid & 7, r0 = tid >> 3;
#pragma unroll
            for (int i = 0; i < 2; ++i) {
                int r = r0 + 32 * i;
                int gr = row0 + r; if (gr > M - 1) gr = M - 1;
                const float4* p = (const float4*)(A + (size_t)gr * K + ch * CK + q * 8);
                float4 va = p[0], vb = p[1];
                float f[8] = {va.x, va.y, va.z, va.w, vb.x, vb.y, vb.z, vb.w};
                float h[8], l[8];
#pragma unroll
                for (int j = 0; j < 8; ++j) {
                    h[j] = __bfloat162float(__float2bfloat16(f[j]));
                    l[j] = f[j] - h[j];
                }
                uint4 HI = {pack_bf16(h[0], h[1]), pack_bf16(h[2], h[3]),
                            pack_bf16(h[4], h[5]), pack_bf16(h[6], h[7])};
                uint4 LO = {pack_bf16(l[0], l[1]), pack_bf16(l[2], l[3]),
                            pack_bf16(l[4], l[5]), pack_bf16(l[6], l[7])};
                *(uint4*)(As + r * STR + q * 8)      = HI;
                *(uint4*)(As + r * STR + CK + q * 8) = LO;
            }
        }
        // B chunk: hi from cols [ch*CK, +CK), lo from [K + ch*CK, +CK)
        for (int u = tid; u < N * 16; u += 256) {
            int n = u >> 4, hgrp = u & 15;
            int srcCol = (hgrp < 8) ? (ch * CK + hgrp * 8) : (K + ch * CK + (hgrp - 8) * 8);
            *(uint4*)(Bs + n * STR + hgrp * 8) = *(const uint4*)(B + n * 2 * K + srcCol);
        }
        __syncthreads();

        const int aoffs[3] = {0, CK, 0};   // (Ah,Bh) (Al,Bh) (Ah,Bl)
        const int boffs[3] = {0, 0, CK};
#pragma unroll
        for (int seg = 0; seg < 3; ++seg) {
#pragma unroll
            for (int ks = 0; ks < CK / 16; ++ks) {
                uint32_t a[4];
                ldsm4(a[0], a[1], a[2], a[3],
                      As_u + (uint32_t)(((wr * 16 + lr + (sel & 1) * 8) * STR +
                                         aoffs[seg] + ks * 16 + (sel >> 1) * 8) * 2));
#pragma unroll
                for (int np = 0; np < NT / 2; ++np) {
                    uint32_t b0, b1, b2, b3;
                    ldsm4(b0, b1, b2, b3,
                          Bs_u + (uint32_t)(((wc * (N / 2) + np * 16 + lr + (sel >> 1) * 8) * STR +
                                             boffs[seg] + ks * 16 + (sel & 1) * 8) * 2));
                    mma16816(d[2 * np],     a, b0, b1);
                    mma16816(d[2 * np + 1], a, b2, b3);
                }
            }
        }
    }

    const int g = lane >> 2, t = lane & 3;
    const int r1 = row0 + wr * 16 + g, r2 = r1 + 8;
#pragma unroll
    for (int nt = 0; nt < NT; ++nt) {
        int col = wc * (N / 2) + nt * 8 + 2 * t;
        if (r1 < M) *(float2*)(C + (size_t)r1 * N + col) = make_float2(d[nt][0], d[nt][1]);
        if (r2 < M) *(float2*)(C + (size_t)r2 * N + col) = make_float2(d[nt][2], d[nt][3]);
    }
}

// wrappers reference device globals FROM DEVICE CODE (the R5/R6 fix)
__global__ void __launch_bounds__(256) k_gemm_paper(const float* __restrict__ A) {
    gemm_body<128, 96>(A, g_WbP, g_P, NP);
}
__global__ void __launch_bounds__(256) k_gemm_author(const float* __restrict__ A) {
    gemm_body<64, 64>(A, g_WbA, g_A, NA);
}

// ---------------- layer-1 gathers fused with layer-2 scalar projections ----------------
__device__ __forceinline__ float gather_mean32(const int* __restrict__ col, int d,
                                               const float* __restrict__ base, int stride,
                                               int lane) {
    float acc = 0.f;
    for (int e = 0; e < d; e += 4) {
        int i0 = __ldg(col + e);
        int i1 = 0, i2 = 0, i3 = 0;
        if (e + 1 < d) i1 = __ldg(col + e + 1);
        if (e + 2 < d) i2 = __ldg(col + e + 2);
        if (e + 3 < d) i3 = __ldg(col + e + 3);
        float v0 = __ldg(base + i0 * stride + lane);
        float v1 = 0.f, v2 = 0.f, v3 = 0.f;
        if (e + 1 < d) v1 = __ldg(base + i1 * stride + lane);
        if (e + 2 < d) v2 = __ldg(base + i2 * stride + lane);
        if (e + 3 < d) v3 = __ldg(base + i3 * stride + lane);
        acc += (v0 + v1) + (v2 + v3);
    }
    return acc / fmaxf((float)d, 1.f);
}

__global__ void __launch_bounds__(256) k_paper() {
    int w = blockIdx.x * 8 + (threadIdx.x >> 5);
    if (w >= NP) return;
    int lane = threadIdx.x & 31;

    int s  = __ldg(&g_rp[w]);      int d  = __ldg(&g_deg[w]);
    int s2 = __ldg(&g_rp[NP + w]); int d2 = __ldg(&g_deg[NP + w]);

    float mc = gather_mean32(g_col + s, d, g_P, 96, lane);
    float mw = gather_mean32(g_col + EE + s2, d2, g_A, 64, lane);

    float p = mc + mw + __ldg(g_P + (size_t)w * 96 + 64 + lane) + g_b1[lane];
    p = fmaxf(p, 0.f);
    float zc = p * g_uc[lane];
    float zr = p * g_wr2[lane];
#pragma unroll
    for (int o = 16; o; o >>= 1) {
        zc += __shfl_xor_sync(0xFFFFFFFFu, zc, o);
        zr += __shfl_xor_sync(0xFFFFFFFFu, zr, o);
    }
    if (lane == 0) { g_zc[w] = zc; g_zr[w] = zr; }
}

__global__ void __launch_bounds__(256) k_author() {
    int w = blockIdx.x * 8 + (threadIdx.x >> 5);
    if (w >= NA) return;
    int lane = threadIdx.x & 31;

    int s = __ldg(&g_rp[2 * NP + w]); int d = __ldg(&g_deg[2 * NP + w]);
    float mr = gather_mean32(g_col + 2 * EE + s, d, g_P + 32, 96, lane);

    float a1 = mr + __ldg(g_A + (size_t)w * 64 + 32 + lane) + g_brev[lane];
    a1 = fmaxf(a1, 0.f);
    float zw = a1 * g_uw[lane];
#pragma unroll
    for (int o = 16; o; o >>= 1) zw += __shfl_xor_sync(0xFFFFFFFFu, zw, o);
    if (lane == 0) g_zw[w] = zw;
}

// ---------------- layer 2 scalar aggregation + head ----------------
__device__ __forceinline__ float gather_mean1(const int* __restrict__ col, int d,
                                              const float* __restrict__ z) {
    float acc = 0.f;
    for (int e = 0; e < d; e += 4) {
        int i0 = __ldg(col + e);
        int i1 = 0, i2 = 0, i3 = 0;
        if (e + 1 < d) i1 = __ldg(col + e + 1);
        if (e + 2 < d) i2 = __ldg(col + e + 2);
        if (e + 3 < d) i3 = __ldg(col + e + 3);
        float v0 = __ldg(z + i0);
        float v1 = 0.f, v2 = 0.f, v3 = 0.f;
        if (e + 1 < d) v1 = __ldg(z + i1);
        if (e + 2 < d) v2 = __ldg(z + i2);
        if (e + 3 < d) v3 = __ldg(z + i3);
        acc += (v0 + v1) + (v2 + v3);
    }
    return acc / fmaxf((float)d, 1.f);
}

__global__ void __launch_bounds__(256) k_out(float* __restrict__ out) {
    int i = blockIdx.x * blockDim.x + threadIdx.x;
    if (i >= NP) return;
    int s  = __ldg(&g_rp[i]);      int d  = __ldg(&g_deg[i]);
    int s2 = __ldg(&g_rp[NP + i]); int d2 = __ldg(&g_deg[NP + i]);
    float sc = gather_mean1(g_col + s, d, g_zc);
    float sw = gather_mean1(g_col + EE + s2, d2, g_zw);
    out[i] = sc + sw + __ldg(&g_zr[i]) + g_cbias;
}

// ---------------- launch ----------------
extern "C" void kernel_launch(void* const* d_in, const int* in_sizes, int n_in,
                              void* d_out, int out_size) {
    const float* x_paper  = (const float*)d_in[0];
    const float* x_author = (const float*)d_in[1];
    const int*   ei_c     = (const int*)d_in[2];
    const int*   ei_w     = (const int*)d_in[3];
    const int*   ei_r     = (const int*)d_in[4];
    float* out = (float*)d_out;

    k_zero<<<(2 * NP + NA + 255) / 256, 256>>>();                              // 0
    k_prep<<<48, 256>>>((const float*)d_in[5],  (const float*)d_in[6],  (const float*)d_in[7],
                        (const float*)d_in[8],  (const float*)d_in[9],  (const float*)d_in[10],
                        (const float*)d_in[11], (const float*)d_in[12], (const float*)d_in[13],
                        (const float*)d_in[14], (const float*)d_in[15], (const float*)d_in[16],
                        (const float*)d_in[17], (const float*)d_in[18], (const float*)d_in[19],
                        (const float*)d_in[23], (const float*)d_in[24]);       // 1
    k_hist3<<<(3 * EE + 255) / 256, 256>>>(ei_c + EE, ei_w + EE, ei_r + EE);   // 2
    k_gemm_paper<<<(NP + 63) / 64, 256>>>(x_paper);                            // 3 (profiled slot)
    k_gemm_author<<<(NA + 63) / 64, 256>>>(x_author);                          // 4
    k_alloc3<<<490, 256>>>();                                                  // 5
    k_fill3<<<(3 * EE + 255) / 256, 256>>>(ei_c, ei_c + EE, ei_w, ei_w + EE, ei_r, ei_r + EE); // 6
    k_paper<<<(NP + 7) / 8, 256>>>();                                          // 7
    k_author<<<(NA + 7) / 8, 256>>>();                                         // 8
    k_out<<<(NP + 255) / 256, 256>>>(out);                                     // 9
}

// round 8
// speedup vs baseline: 1.7118x; 1.0896x over previous
#include <cuda_runtime.h>
#include <cuda_bf16.h>
#include <cstdint>

#define NP 200000
#define NA 100000
#define EE 1000000
#define HH 32

#define GEMM_BLKS_P 1563          // (NP+127)/128
#define GEMM_BLKS_A 782           // (NA+127)/128
#define ZERO_BLKS 1954            // (2*NP+NA+255)/256
#define PA_BLKS_P 25000           // NP/8
#define PA_BLKS_A 12500           // NA/8

// ---------------- device scratch ----------------
__device__ int g_deg[2 * NP + NA];
__device__ int g_cur[2 * NP + NA];
__device__ int g_rp [2 * NP + NA];
__device__ int g_cnt[3];
__device__ int g_col[3 * EE];

__device__ __align__(16) float g_P[(size_t)NP * 96];
__device__ __align__(16) float g_A[(size_t)NA * 64];
__device__ float g_zc[NP], g_zr[NP], g_zw[NA];

// bf16 split B images, row-major [N][2K]: cols 0..K-1 = hi(W), K..2K-1 = lo(W)
__device__ __align__(16) __nv_bfloat16 g_WbP[96 * 256];
__device__ __align__(16) __nv_bfloat16 g_WbA[64 * 128];
__device__ float g_b1[HH], g_brev[HH], g_uc[HH], g_uw[HH], g_wr2[HH];
__device__ float g_cbias;

// ---------------- helpers ----------------
__device__ __forceinline__ uint32_t smem_u32(const void* p) {
    uint32_t a;
    asm("{ .reg .u64 t; cvta.to.shared.u64 t, %1; cvt.u32.u64 %0, t; }" : "=r"(a) : "l"(p));
    return a;
}
__device__ __forceinline__ unsigned int pack_bf16(float a, float b) {
    __nv_bfloat162 h = __floats2bfloat162_rn(a, b);
    return *reinterpret_cast<unsigned int*>(&h);
}
__device__ __forceinline__ void ldsm4(uint32_t& r0, uint32_t& r1, uint32_t& r2, uint32_t& r3,
                                      uint32_t addr) {
    asm volatile("ldmatrix.sync.aligned.m8n8.x4.shared.b16 {%0,%1,%2,%3}, [%4];"
                 : "=r"(r0), "=r"(r1), "=r"(r2), "=r"(r3) : "r"(addr));
}
__device__ __forceinline__ void mma16816(float* d, const uint32_t* a, uint32_t b0, uint32_t b1) {
    asm volatile(
        "mma.sync.aligned.m16n8k16.row.col.f32.bf16.bf16.f32 "
        "{%0,%1,%2,%3}, {%4,%5,%6,%7}, {%8,%9}, {%0,%1,%2,%3};"
        : "+f"(d[0]), "+f"(d[1]), "+f"(d[2]), "+f"(d[3])
        : "r"(a[0]), "r"(a[1]), "r"(a[2]), "r"(a[3]), "r"(b0), "r"(b1));
}

// ---------------- init + weight prep (merged) ----------------
__global__ void k_init(const float* __restrict__ W1l_c,  const float* __restrict__ b1l_c,
                       const float* __restrict__ W1r_c,  const float* __restrict__ W1l_w,
                       const float* __restrict__ b1l_w,  const float* __restrict__ W1r_w,
                       const float* __restrict__ W1l_rev,const float* __restrict__ b1l_rev,
                       const float* __restrict__ W1r_rev,const float* __restrict__ W2l_c,
                       const float* __restrict__ b2l_c,  const float* __restrict__ W2r_c,
                       const float* __restrict__ W2l_w,  const float* __restrict__ b2l_w,
                       const float* __restrict__ W2r_w,  const float* __restrict__ Wh,
                       const float* __restrict__ bh) {
    int b = blockIdx.x;
    if (b < ZERO_BLKS) {
        int i = b * 256 + threadIdx.x;
        if (i < 2 * NP + NA) g_deg[i] = 0;
        if (i < 3) g_cnt[i] = 0;
        return;
    }
    int idx = (b - ZERO_BLKS) * 256 + threadIdx.x;
    const int stride = 48 * 256;

    for (int q = idx; q < 96 * 256; q += stride) {
        int n = q >> 8, kc = q & 255;
        int k = kc & 127;
        bool lo = kc >= 128;
        float v;
        if (n < 32)      v = W1l_c[k * HH + n];
        else if (n < 64) v = W1l_rev[k * HH + n - 32];
        else             v = W1r_c[k * HH + n - 64] + W1r_w[k * HH + n - 64];
        __nv_bfloat16 h = __float2bfloat16(v);
        g_WbP[q] = lo ? __float2bfloat16(v - __bfloat162float(h)) : h;
    }
    for (int q = idx; q < 64 * 128; q += stride) {
        int n = q >> 7, kc = q & 127;
        int k = kc & 63;
        bool lo = kc >= 64;
        float v = (n < 32) ? W1l_w[k * HH + n] : W1r_rev[k * HH + n - 32];
        __nv_bfloat16 h = __float2bfloat16(v);
        g_WbA[q] = lo ? __float2bfloat16(v - __bfloat162float(h)) : h;
    }
    if (idx < HH) {
        g_b1[idx]   = b1l_c[idx] + b1l_w[idx];
        g_brev[idx] = b1l_rev[idx];
        float uc = 0.f, uw = 0.f, wr = 0.f;
        for (int j = 0; j < HH; ++j) {
            float wh = Wh[j];
            uc += W2l_c[idx * HH + j] * wh;
            uw += W2l_w[idx * HH + j] * wh;
            wr += (W2r_c[idx * HH + j] + W2r_w[idx * HH + j]) * wh;
        }
        g_uc[idx] = uc; g_uw[idx] = uw; g_wr2[idx] = wr;
    }
    if (idx == 0) {
        float cb = bh[0];
        for (int j = 0; j < HH; ++j) cb += (b2l_c[j] + b2l_w[j]) * Wh[j];
        g_cbias = cb;
    }
}

// ---------------- CSR build ----------------
__global__ void k_hist3(const int* __restrict__ dc, const int* __restrict__ dw,
                        const int* __restrict__ dr) {
    int e = blockIdx.x * blockDim.x + threadIdx.x;
    if (e < EE)            atomicAdd(&g_deg[__ldg(dc + e)], 1);
    else if (e < 2 * EE)   atomicAdd(&g_deg[NP + __ldg(dw + e - EE)], 1);
    else if (e < 3 * EE)   atomicAdd(&g_deg[2 * NP + __ldg(dr + e - 2 * EE)], 1);
}

__global__ void k_alloc3() {
    __shared__ int sm[256];
    __shared__ int sbase;
    int b = blockIdx.x;
    int off, n, cidx, lb;
    if (b < 196)      { off = 0;      n = NP; cidx = 0; lb = b; }
    else if (b < 392) { off = NP;     n = NP; cidx = 1; lb = b - 196; }
    else              { off = 2 * NP; n = NA; cidx = 2; lb = b - 392; }

    int t = threadIdx.x;
    int idx0 = lb * 1024 + t * 4;
    int d0 = (idx0 + 0 < n) ? g_deg[off + idx0 + 0] : 0;
    int d1 = (idx0 + 1 < n) ? g_deg[off + idx0 + 1] : 0;
    int d2 = (idx0 + 2 < n) ? g_deg[off + idx0 + 2] : 0;
    int d3 = (idx0 + 3 < n) ? g_deg[off + idx0 + 3] : 0;
    int s = d0 + d1 + d2 + d3;
    sm[t] = s;
    __syncthreads();
    for (int o = 1; o < 256; o <<= 1) {
        int v = (t >= o) ? sm[t - o] : 0;
        __syncthreads();
        sm[t] += v;
        __syncthreads();
    }
    if (t == 255) sbase = atomicAdd(&g_cnt[cidx], sm[255]);
    __syncthreads();
    int start = sbase + sm[t] - s;
    if (idx0 + 0 < n) { g_rp[off + idx0 + 0] = start; g_cur[off + idx0 + 0] = start; start += d0; }
    if (idx0 + 1 < n) { g_rp[off + idx0 + 1] = start; g_cur[off + idx0 + 1] = start; start += d1; }
    if (idx0 + 2 < n) { g_rp[off + idx0 + 2] = start; g_cur[off + idx0 + 2] = start; start += d2; }
    if (idx0 + 3 < n) { g_rp[off + idx0 + 3] = start; g_cur[off + idx0 + 3] = start; }
}

__global__ void k_fill3(const int* __restrict__ sc, const int* __restrict__ dc,
                        const int* __restrict__ sw, const int* __restrict__ dw,
                        const int* __restrict__ sr, const int* __restrict__ dr) {
    int e = blockIdx.x * blockDim.x + threadIdx.x;
    const int* s; const int* d; int off, colOff, le;
    if (e < EE)          { s = sc; d = dc; off = 0;      colOff = 0;      le = e; }
    else if (e < 2 * EE) { s = sw; d = dw; off = NP;     colOff = EE;     le = e - EE; }
    else if (e < 3 * EE) { s = sr; d = dr; off = 2 * NP; colOff = 2 * EE; le = e - 2 * EE; }
    else return;
    int dd = __ldg(d + le);
    int p = atomicAdd(&g_cur[off + dd], 1);
    g_col[colOff + p] = __ldg(s + le);
}

// ---------------- bf16 3-term-split GEMM, BM=128, CK=32, 32-row warps ----------------
// Warp (wr=warp&3, wc=warp>>2) owns rows wr*32..+31, cols wc*(N/2)..+N/2-1.
// Per (seg,ks): 2 A-ldsm + (N/32) B-ldsm feed 4*(N/32) MMAs (vs 1+3:6 before).
template <int K, int N>
__device__ __forceinline__ void gemm_body(const float* __restrict__ A,
                                          const __nv_bfloat16* __restrict__ B, // [N][2K]
                                          float* __restrict__ C, int M, int row0,
                                          __nv_bfloat16* As, __nv_bfloat16* Bs) {
    constexpr int CK  = 32;
    constexpr int NCH = K / CK;
    constexpr int STR = 2 * CK + 8;   // 72
    constexpr int NP2 = N / 32;       // B-ldsm (16-col groups) per warp half
    constexpr int NT  = N / 16;       // accum col-8-tiles per warp

    const int tid = threadIdx.x;
    const int warp = tid >> 5, lane = tid & 31;
    const int wr = warp & 3, wc = warp >> 2;
    const int lr = lane & 7, sel = lane >> 3;
    const uint32_t As_u = smem_u32(As), Bs_u = smem_u32(Bs);

    float d[2][NT][4];
#pragma unroll
    for (int rg = 0; rg < 2; ++rg)
#pragma unroll
        for (int nt = 0; nt < NT; ++nt)
#pragma unroll
            for (int j = 0; j < 4; ++j) d[rg][nt][j] = 0.f;

#pragma unroll
    for (int ch = 0; ch < NCH; ++ch) {
        __syncthreads();
        // A chunk: 128 rows x 32 f32, split hi/lo. q=tid&3 col-octet, r0=tid>>2.
        {
            const int q = tid & 3, r0 = tid >> 2;
#pragma unroll
            for (int i = 0; i < 2; ++i) {
                int r = r0 + 64 * i;
                int gr = row0 + r; if (gr > M - 1) gr = M - 1;
                const float4* p = (const float4*)(A + (size_t)gr * K + ch * CK + q * 8);
                float4 va = p[0], vb = p[1];
                float f[8] = {va.x, va.y, va.z, va.w, vb.x, vb.y, vb.z, vb.w};
                float h[8], l[8];
#pragma unroll
                for (int j = 0; j < 8; ++j) {
                    h[j] = __bfloat162float(__float2bfloat16(f[j]));
                    l[j] = f[j] - h[j];
                }
                uint4 HI = {pack_bf16(h[0], h[1]), pack_bf16(h[2], h[3]),
                            pack_bf16(h[4], h[5]), pack_bf16(h[6], h[7])};
                uint4 LO = {pack_bf16(l[0], l[1]), pack_bf16(l[2], l[3]),
                            pack_bf16(l[4], l[5]), pack_bf16(l[6], l[7])};
                *(uint4*)(As + r * STR + q * 8)      = HI;
                *(uint4*)(As + r * STR + CK + q * 8) = LO;
            }
        }
        // B chunk: grp 0-3 = hi cols, 4-7 = lo cols
        for (int u = tid; u < N * 8; u += 256) {
            int n = u >> 3, grp = u & 7;
            int srcCol = (grp < 4) ? (ch * CK + grp * 8) : (K + ch * CK + (grp - 4) * 8);
            *(uint4*)(Bs + n * STR + grp * 8) = *(const uint4*)(B + n * 2 * K + srcCol);
        }
        __syncthreads();

        const int aoffs[3] = {0, CK, 0};   // (Ah,Bh) (Al,Bh) (Ah,Bl)
        const int boffs[3] = {0, 0, CK};
#pragma unroll
        for (int seg = 0; seg < 3; ++seg) {
#pragma unroll
            for (int ks = 0; ks < CK / 16; ++ks) {
                uint32_t a[2][4];
#pragma unroll
                for (int rg = 0; rg < 2; ++rg)
                    ldsm4(a[rg][0], a[rg][1], a[rg][2], a[rg][3],
                          As_u + (uint32_t)(((wr * 32 + rg * 16 + lr + (sel & 1) * 8) * STR +
                                             aoffs[seg] + ks * 16 + (sel >> 1) * 8) * 2));
#pragma unroll
                for (int np = 0; np < NP2; ++np) {
                    uint32_t b0, b1, b2, b3;
                    ldsm4(b0, b1, b2, b3,
                          Bs_u + (uint32_t)(((wc * (N / 2) + np * 16 + lr + (sel >> 1) * 8) * STR +
                                             boffs[seg] + ks * 16 + (sel & 1) * 8) * 2));
#pragma unroll
                    for (int rg = 0; rg < 2; ++rg) {
                        mma16816(d[rg][2 * np],     a[rg], b0, b1);
                        mma16816(d[rg][2 * np + 1], a[rg], b2, b3);
                    }
                }
            }
        }
    }

    const int g = lane >> 2, t = lane & 3;
#pragma unroll
    for (int rg = 0; rg < 2; ++rg) {
        const int r1 = row0 + wr * 32 + rg * 16 + g, r2 = r1 + 8;
#pragma unroll
        for (int nt = 0; nt < NT; ++nt) {
            int col = wc * (N / 2) + nt * 8 + 2 * t;
            if (r1 < M) *(float2*)(C + (size_t)r1 * N + col) = make_float2(d[rg][nt][0], d[rg][nt][1]);
            if (r2 < M) *(float2*)(C + (size_t)r2 * N + col) = make_float2(d[rg][nt][2], d[rg][nt][3]);
        }
    }
}

__global__ void __launch_bounds__(256, 2) k_gemm_all(const float* __restrict__ xp,
                                                     const float* __restrict__ xa) {
    __shared__ __nv_bfloat16 sm[128 * 72 + 96 * 72];   // As + Bs(union), 32.25KB
    if (blockIdx.x < GEMM_BLKS_P)
        gemm_body<128, 96>(xp, g_WbP, g_P, NP, blockIdx.x * 128, sm, sm + 128 * 72);
    else
        gemm_body<64, 64>(xa, g_WbA, g_A, NA, (blockIdx.x - GEMM_BLKS_P) * 128, sm, sm + 128 * 72);
}

// ---------------- layer-1 gathers + layer-2 scalar projections (merged) ----------------
__device__ __forceinline__ float gather_mean32(const int* __restrict__ col, int d,
                                               const float* __restrict__ base, int stride,
                                               int lane) {
    float acc = 0.f;
    for (int e = 0; e < d; e += 4) {
        int i0 = __ldg(col + e);
        int i1 = 0, i2 = 0, i3 = 0;
        if (e + 1 < d) i1 = __ldg(col + e + 1);
        if (e + 2 < d) i2 = __ldg(col + e + 2);
        if (e + 3 < d) i3 = __ldg(col + e + 3);
        float v0 = __ldg(base + i0 * stride + lane);
        float v1 = 0.f, v2 = 0.f, v3 = 0.f;
        if (e + 1 < d) v1 = __ldg(base + i1 * stride + lane);
        if (e + 2 < d) v2 = __ldg(base + i2 * stride + lane);
        if (e + 3 < d) v3 = __ldg(base + i3 * stride + lane);
        acc += (v0 + v1) + (v2 + v3);
    }
    return acc / fmaxf((float)d, 1.f);
}

__global__ void __launch_bounds__(256) k_pa() {
    int lane = threadIdx.x & 31;
    if (blockIdx.x < PA_BLKS_P) {
        int w = blockIdx.x * 8 + (threadIdx.x >> 5);
        int s  = __ldg(&g_rp[w]);      int d  = __ldg(&g_deg[w]);
        int s2 = __ldg(&g_rp[NP + w]); int d2 = __ldg(&g_deg[NP + w]);

        float mc = gather_mean32(g_col + s, d, g_P, 96, lane);
        float mw = gather_mean32(g_col + EE + s2, d2, g_A, 64, lane);

        float p = mc + mw + __ldg(g_P + (size_t)w * 96 + 64 + lane) + g_b1[lane];
        p = fmaxf(p, 0.f);
        float zc = p * g_uc[lane];
        float zr = p * g_wr2[lane];
#pragma unroll
        for (int o = 16; o; o >>= 1) {
            zc += __shfl_xor_sync(0xFFFFFFFFu, zc, o);
            zr += __shfl_xor_sync(0xFFFFFFFFu, zr, o);
        }
        if (lane == 0) { g_zc[w] = zc; g_zr[w] = zr; }
    } else {
        int w = (blockIdx.x - PA_BLKS_P) * 8 + (threadIdx.x >> 5);
        int s = __ldg(&g_rp[2 * NP + w]); int d = __ldg(&g_deg[2 * NP + w]);
        float mr = gather_mean32(g_col + 2 * EE + s, d, g_P + 32, 96, lane);

        float a1 = mr + __ldg(g_A + (size_t)w * 64 + 32 + lane) + g_brev[lane];
        a1 = fmaxf(a1, 0.f);
        float zw = a1 * g_uw[lane];
#pragma unroll
        for (int o = 16; o; o >>= 1) zw += __shfl_xor_sync(0xFFFFFFFFu, zw, o);
        if (lane == 0) g_zw[w] = zw;
    }
}

// ---------------- layer 2 scalar aggregation + head ----------------
__device__ __forceinline__ float gather_mean1(const int* __restrict__ col, int d,
                                              const float* __restrict__ z) {
    float acc = 0.f;
    for (int e = 0; e < d; e += 4) {
        int i0 = __ldg(col + e);
        int i1 = 0, i2 = 0, i3 = 0;
        if (e + 1 < d) i1 = __ldg(col + e + 1);
        if (e + 2 < d) i2 = __ldg(col + e + 2);
        if (e + 3 < d) i3 = __ldg(col + e + 3);
        float v0 = __ldg(z + i0);
        float v1 = 0.f, v2 = 0.f, v3 = 0.f;
        if (e + 1 < d) v1 = __ldg(z + i1);
        if (e + 2 < d) v2 = __ldg(z + i2);
        if (e + 3 < d) v3 = __ldg(z + i3);
        acc += (v0 + v1) + (v2 + v3);
    }
    return acc / fmaxf((float)d, 1.f);
}

__global__ void __launch_bounds__(256) k_out(float* __restrict__ out) {
    int i = blockIdx.x * blockDim.x + threadIdx.x;
    if (i >= NP) return;
    int s  = __ldg(&g_rp[i]);      int d  = __ldg(&g_deg[i]);
    int s2 = __ldg(&g_rp[NP + i]); int d2 = __ldg(&g_deg[NP + i]);
    float sc = gather_mean1(g_col + s, d, g_zc);
    float sw = gather_mean1(g_col + EE + s2, d2, g_zw);
    out[i] = sc + sw + __ldg(&g_zr[i]) + g_cbias;
}

// ---------------- launch ----------------
extern "C" void kernel_launch(void* const* d_in, const int* in_sizes, int n_in,
                              void* d_out, int out_size) {
    const float* x_paper  = (const float*)d_in[0];
    const float* x_author = (const float*)d_in[1];
    const int*   ei_c     = (const int*)d_in[2];
    const int*   ei_w     = (const int*)d_in[3];
    const int*   ei_r     = (const int*)d_in[4];
    float* out = (float*)d_out;

    k_init<<<ZERO_BLKS + 48, 256>>>(
        (const float*)d_in[5],  (const float*)d_in[6],  (const float*)d_in[7],
        (const float*)d_in[8],  (const float*)d_in[9],  (const float*)d_in[10],
        (const float*)d_in[11], (const float*)d_in[12], (const float*)d_in[13],
        (const float*)d_in[14], (const float*)d_in[15], (const float*)d_in[16],
        (const float*)d_in[17], (const float*)d_in[18], (const float*)d_in[19],
        (const float*)d_in[23], (const float*)d_in[24]);                       // 0
    k_hist3<<<(3 * EE + 255) / 256, 256>>>(ei_c + EE, ei_w + EE, ei_r + EE);   // 1
    k_alloc3<<<490, 256>>>();                                                  // 2
    k_gemm_all<<<GEMM_BLKS_P + GEMM_BLKS_A, 256>>>(x_paper, x_author);         // 3 (profiled slot)
    k_fill3<<<(3 * EE + 255) / 256, 256>>>(ei_c, ei_c + EE, ei_w, ei_w + EE, ei_r, ei_r + EE); // 4
    k_pa<<<PA_BLKS_P + PA_BLKS_A, 256>>>();                                    // 5
    k_out<<<(NP + 255) / 256, 256>>>(out);                                     // 6
}

// round 9
// speedup vs baseline: 1.7877x; 1.0443x over previous
#include <cuda_runtime.h>
#include <cuda_bf16.h>
#include <cstdint>

#define NP 200000
#define NA 100000
#define EE 1000000
#define HH 32

#define GEMM_BLKS_P 1563          // (NP+127)/128
#define GEMM_BLKS_A 782           // (NA+127)/128
#define ZERO_BLKS 1954            // (2*NP+NA+255)/256
#define PA_BLKS_P 25000           // NP/8
#define PA_BLKS_A 12500           // NA/8

// ---------------- device scratch ----------------
__device__ int g_deg[2 * NP + NA];
__device__ int g_cur[2 * NP + NA];
__device__ int g_rp [2 * NP + NA];
__device__ int g_cnt[3];
__device__ int g_col[3 * EE];

__device__ __align__(16) float g_P[(size_t)NP * 96];
__device__ __align__(16) float g_A[(size_t)NA * 64];
__device__ float g_zc[NP], g_zr[NP], g_zw[NA];

// bf16 split B images, row-major [N][2K]: cols 0..K-1 = hi(W), K..2K-1 = lo(W)
__device__ __align__(16) __nv_bfloat16 g_WbP[96 * 256];
__device__ __align__(16) __nv_bfloat16 g_WbA[64 * 128];
__device__ float g_b1[HH], g_brev[HH], g_uc[HH], g_uw[HH], g_wr2[HH];
__device__ float g_cbias;

// ---------------- helpers ----------------
__device__ __forceinline__ uint32_t smem_u32(const void* p) {
    uint32_t a;
    asm("{ .reg .u64 t; cvta.to.shared.u64 t, %1; cvt.u32.u64 %0, t; }" : "=r"(a) : "l"(p));
    return a;
}
__device__ __forceinline__ unsigned int pack_bf16(float a, float b) {
    __nv_bfloat162 h = __floats2bfloat162_rn(a, b);
    return *reinterpret_cast<unsigned int*>(&h);
}
__device__ __forceinline__ void ldsm4(uint32_t& r0, uint32_t& r1, uint32_t& r2, uint32_t& r3,
                                      uint32_t addr) {
    asm volatile("ldmatrix.sync.aligned.m8n8.x4.shared.b16 {%0,%1,%2,%3}, [%4];"
                 : "=r"(r0), "=r"(r1), "=r"(r2), "=r"(r3) : "r"(addr));
}
__device__ __forceinline__ void mma16816(float* d, const uint32_t* a, uint32_t b0, uint32_t b1) {
    asm volatile(
        "mma.sync.aligned.m16n8k16.row.col.f32.bf16.bf16.f32 "
        "{%0,%1,%2,%3}, {%4,%5,%6,%7}, {%8,%9}, {%0,%1,%2,%3};"
        : "+f"(d[0]), "+f"(d[1]), "+f"(d[2]), "+f"(d[3])
        : "r"(a[0]), "r"(a[1]), "r"(a[2]), "r"(a[3]), "r"(b0), "r"(b1));
}

// ---------------- init + weight prep (merged) ----------------
__global__ void k_init(const float* __restrict__ W1l_c,  const float* __restrict__ b1l_c,
                       const float* __restrict__ W1r_c,  const float* __restrict__ W1l_w,
                       const float* __restrict__ b1l_w,  const float* __restrict__ W1r_w,
                       const float* __restrict__ W1l_rev,const float* __restrict__ b1l_rev,
                       const float* __restrict__ W1r_rev,const float* __restrict__ W2l_c,
                       const float* __restrict__ b2l_c,  const float* __restrict__ W2r_c,
                       const float* __restrict__ W2l_w,  const float* __restrict__ b2l_w,
                       const float* __restrict__ W2r_w,  const float* __restrict__ Wh,
                       const float* __restrict__ bh) {
    int b = blockIdx.x;
    if (b < ZERO_BLKS) {
        int i = b * 256 + threadIdx.x;
        if (i < 2 * NP + NA) g_deg[i] = 0;
        if (i < 3) g_cnt[i] = 0;
        return;
    }
    int idx = (b - ZERO_BLKS) * 256 + threadIdx.x;
    const int stride = 48 * 256;

    for (int q = idx; q < 96 * 256; q += stride) {
        int n = q >> 8, kc = q & 255;
        int k = kc & 127;
        bool lo = kc >= 128;
        float v;
        if (n < 32)      v = W1l_c[k * HH + n];
        else if (n < 64) v = W1l_rev[k * HH + n - 32];
        else             v = W1r_c[k * HH + n - 64] + W1r_w[k * HH + n - 64];
        __nv_bfloat16 h = __float2bfloat16(v);
        g_WbP[q] = lo ? __float2bfloat16(v - __bfloat162float(h)) : h;
    }
    for (int q = idx; q < 64 * 128; q += stride) {
        int n = q >> 7, kc = q & 127;
        int k = kc & 63;
        bool lo = kc >= 64;
        float v = (n < 32) ? W1l_w[k * HH + n] : W1r_rev[k * HH + n - 32];
        __nv_bfloat16 h = __float2bfloat16(v);
        g_WbA[q] = lo ? __float2bfloat16(v - __bfloat162float(h)) : h;
    }
    if (idx < HH) {
        g_b1[idx]   = b1l_c[idx] + b1l_w[idx];
        g_brev[idx] = b1l_rev[idx];
        float uc = 0.f, uw = 0.f, wr = 0.f;
        for (int j = 0; j < HH; ++j) {
            float wh = Wh[j];
            uc += W2l_c[idx * HH + j] * wh;
            uw += W2l_w[idx * HH + j] * wh;
            wr += (W2r_c[idx * HH + j] + W2r_w[idx * HH + j]) * wh;
        }
        g_uc[idx] = uc; g_uw[idx] = uw; g_wr2[idx] = wr;
    }
    if (idx == 0) {
        float cb = bh[0];
        for (int j = 0; j < HH; ++j) cb += (b2l_c[j] + b2l_w[j]) * Wh[j];
        g_cbias = cb;
    }
}

// ---------------- CSR build ----------------
__global__ void k_hist3(const int* __restrict__ dc, const int* __restrict__ dw,
                        const int* __restrict__ dr) {
    int e = blockIdx.x * blockDim.x + threadIdx.x;
    if (e < EE)            atomicAdd(&g_deg[__ldg(dc + e)], 1);
    else if (e < 2 * EE)   atomicAdd(&g_deg[NP + __ldg(dw + e - EE)], 1);
    else if (e < 3 * EE)   atomicAdd(&g_deg[2 * NP + __ldg(dr + e - 2 * EE)], 1);
}

__global__ void k_alloc3() {
    __shared__ int sm[256];
    __shared__ int sbase;
    int b = blockIdx.x;
    int off, n, cidx, lb;
    if (b < 196)      { off = 0;      n = NP; cidx = 0; lb = b; }
    else if (b < 392) { off = NP;     n = NP; cidx = 1; lb = b - 196; }
    else              { off = 2 * NP; n = NA; cidx = 2; lb = b - 392; }

    int t = threadIdx.x;
    int idx0 = lb * 1024 + t * 4;
    int d0 = (idx0 + 0 < n) ? g_deg[off + idx0 + 0] : 0;
    int d1 = (idx0 + 1 < n) ? g_deg[off + idx0 + 1] : 0;
    int d2 = (idx0 + 2 < n) ? g_deg[off + idx0 + 2] : 0;
    int d3 = (idx0 + 3 < n) ? g_deg[off + idx0 + 3] : 0;
    int s = d0 + d1 + d2 + d3;
    sm[t] = s;
    __syncthreads();
    for (int o = 1; o < 256; o <<= 1) {
        int v = (t >= o) ? sm[t - o] : 0;
        __syncthreads();
        sm[t] += v;
        __syncthreads();
    }
    if (t == 255) sbase = atomicAdd(&g_cnt[cidx], sm[255]);
    __syncthreads();
    int start = sbase + sm[t] - s;
    if (idx0 + 0 < n) { g_rp[off + idx0 + 0] = start; g_cur[off + idx0 + 0] = start; start += d0; }
    if (idx0 + 1 < n) { g_rp[off + idx0 + 1] = start; g_cur[off + idx0 + 1] = start; start += d1; }
    if (idx0 + 2 < n) { g_rp[off + idx0 + 2] = start; g_cur[off + idx0 + 2] = start; start += d2; }
    if (idx0 + 3 < n) { g_rp[off + idx0 + 3] = start; g_cur[off + idx0 + 3] = start; }
}

__global__ void k_fill3(const int* __restrict__ sc, const int* __restrict__ dc,
                        const int* __restrict__ sw, const int* __restrict__ dw,
                        const int* __restrict__ sr, const int* __restrict__ dr) {
    int e = blockIdx.x * blockDim.x + threadIdx.x;
    const int* s; const int* d; int off, colOff, le;
    if (e < EE)          { s = sc; d = dc; off = 0;      colOff = 0;      le = e; }
    else if (e < 2 * EE) { s = sw; d = dw; off = NP;     colOff = EE;     le = e - EE; }
    else if (e < 3 * EE) { s = sr; d = dr; off = 2 * NP; colOff = 2 * EE; le = e - 2 * EE; }
    else return;
    int dd = __ldg(d + le);
    int p = atomicAdd(&g_cur[off + dd], 1);
    g_col[colOff + p] = __ldg(s + le);
}

// ---------------- bf16 3-term-split GEMM, fragment-shared inner loop ----------------
// Per K-16 slice: load Ah,Bh -> MMA; load Al -> MMA(Al,Bh); load Bl -> MMA(Ah,Bl).
// 10 ldsm per slice for 12*NP2 MMAs (was 15).
template <int K, int N>
__device__ __forceinline__ void gemm_body(const float* __restrict__ A,
                                          const __nv_bfloat16* __restrict__ B, // [N][2K]
                                          float* __restrict__ C, int M, int row0,
                                          __nv_bfloat16* As, __nv_bfloat16* Bs) {
    constexpr int CK  = 32;
    constexpr int NCH = K / CK;
    constexpr int STR = 2 * CK + 8;   // 72
    constexpr int NP2 = N / 32;
    constexpr int NT  = N / 16;

    const int tid = threadIdx.x;
    const int warp = tid >> 5, lane = tid & 31;
    const int wr = warp & 3, wc = warp >> 2;
    const int lr = lane & 7, sel = lane >> 3;
    const uint32_t As_u = smem_u32(As), Bs_u = smem_u32(Bs);

    float d[2][NT][4];
#pragma unroll
    for (int rg = 0; rg < 2; ++rg)
#pragma unroll
        for (int nt = 0; nt < NT; ++nt)
#pragma unroll
            for (int j = 0; j < 4; ++j) d[rg][nt][j] = 0.f;

#pragma unroll
    for (int ch = 0; ch < NCH; ++ch) {
        __syncthreads();
        // A chunk: 128 rows x 32 f32, split hi/lo
        {
            const int q = tid & 3, r0 = tid >> 2;
#pragma unroll
            for (int i = 0; i < 2; ++i) {
                int r = r0 + 64 * i;
                int gr = row0 + r; if (gr > M - 1) gr = M - 1;
                const float4* p = (const float4*)(A + (size_t)gr * K + ch * CK + q * 8);
                float4 va = p[0], vb = p[1];
                float f[8] = {va.x, va.y, va.z, va.w, vb.x, vb.y, vb.z, vb.w};
                float h[8], l[8];
#pragma unroll
                for (int j = 0; j < 8; ++j) {
                    h[j] = __bfloat162float(__float2bfloat16(f[j]));
                    l[j] = f[j] - h[j];
                }
                uint4 HI = {pack_bf16(h[0], h[1]), pack_bf16(h[2], h[3]),
                            pack_bf16(h[4], h[5]), pack_bf16(h[6], h[7])};
                uint4 LO = {pack_bf16(l[0], l[1]), pack_bf16(l[2], l[3]),
                            pack_bf16(l[4], l[5]), pack_bf16(l[6], l[7])};
                *(uint4*)(As + r * STR + q * 8)      = HI;
                *(uint4*)(As + r * STR + CK + q * 8) = LO;
            }
        }
        // B chunk: grp 0-3 = hi cols, 4-7 = lo cols
        for (int u = tid; u < N * 8; u += 256) {
            int n = u >> 3, grp = u & 7;
            int srcCol = (grp < 4) ? (ch * CK + grp * 8) : (K + ch * CK + (grp - 4) * 8);
            *(uint4*)(Bs + n * STR + grp * 8) = *(const uint4*)(B + n * 2 * K + srcCol);
        }
        __syncthreads();

#pragma unroll
        for (int ks = 0; ks < CK / 16; ++ks) {
            const uint32_t a_base = As_u + (uint32_t)(((wr * 32 + lr + (sel & 1) * 8) * STR +
                                                       ks * 16 + (sel >> 1) * 8) * 2);
            const uint32_t b_base = Bs_u + (uint32_t)(((wc * (N / 2) + lr + (sel >> 1) * 8) * STR +
                                                       ks * 16 + (sel & 1) * 8) * 2);
            uint32_t ah[2][4], al[2][4], bh[NP2][4], bl[NP2][4];
            // Ah + Bh
#pragma unroll
            for (int rg = 0; rg < 2; ++rg)
                ldsm4(ah[rg][0], ah[rg][1], ah[rg][2], ah[rg][3],
                      a_base + (uint32_t)(rg * 16 * STR * 2));
#pragma unroll
            for (int np = 0; np < NP2; ++np)
                ldsm4(bh[np][0], bh[np][1], bh[np][2], bh[np][3],
                      b_base + (uint32_t)(np * 16 * STR * 2));
#pragma unroll
            for (int np = 0; np < NP2; ++np)
#pragma unroll
                for (int rg = 0; rg < 2; ++rg) {
                    mma16816(d[rg][2 * np],     ah[rg], bh[np][0], bh[np][1]);
                    mma16816(d[rg][2 * np + 1], ah[rg], bh[np][2], bh[np][3]);
                }
            // Al x Bh
#pragma unroll
            for (int rg = 0; rg < 2; ++rg)
                ldsm4(al[rg][0], al[rg][1], al[rg][2], al[rg][3],
                      a_base + (uint32_t)((rg * 16 * STR + CK) * 2));
#pragma unroll
            for (int np = 0; np < NP2; ++np)
#pragma unroll
                for (int rg = 0; rg < 2; ++rg) {
                    mma16816(d[rg][2 * np],     al[rg], bh[np][0], bh[np][1]);
                    mma16816(d[rg][2 * np + 1], al[rg], bh[np][2], bh[np][3]);
                }
            // Ah x Bl
#pragma unroll
            for (int np = 0; np < NP2; ++np)
                ldsm4(bl[np][0], bl[np][1], bl[np][2], bl[np][3],
                      b_base + (uint32_t)((np * 16 * STR + CK) * 2));
#pragma unroll
            for (int np = 0; np < NP2; ++np)
#pragma unroll
                for (int rg = 0; rg < 2; ++rg) {
                    mma16816(d[rg][2 * np],     ah[rg], bl[np][0], bl[np][1]);
                    mma16816(d[rg][2 * np + 1], ah[rg], bl[np][2], bl[np][3]);
                }
        }
    }

    const int g = lane >> 2, t = lane & 3;
#pragma unroll
    for (int rg = 0; rg < 2; ++rg) {
        const int r1 = row0 + wr * 32 + rg * 16 + g, r2 = r1 + 8;
#pragma unroll
        for (int nt = 0; nt < NT; ++nt) {
            int col = wc * (N / 2) + nt * 8 + 2 * t;
            if (r1 < M) *(float2*)(C + (size_t)r1 * N + col) = make_float2(d[rg][nt][0], d[rg][nt][1]);
            if (r2 < M) *(float2*)(C + (size_t)r2 * N + col) = make_float2(d[rg][nt][2], d[rg][nt][3]);
        }
    }
}

__global__ void __launch_bounds__(256, 2) k_gemm_all(const float* __restrict__ xp,
                                                     const float* __restrict__ xa) {
    __shared__ __nv_bfloat16 sm[128 * 72 + 96 * 72];
    if (blockIdx.x < GEMM_BLKS_P)
        gemm_body<128, 96>(xp, g_WbP, g_P, NP, blockIdx.x * 128, sm, sm + 128 * 72);
    else
        gemm_body<64, 64>(xa, g_WbA, g_A, NA, (blockIdx.x - GEMM_BLKS_P) * 128, sm, sm + 128 * 72);
}

// ---------------- layer-1 gathers + layer-2 scalar projections (merged, MLP=8) ----------------
__device__ __forceinline__ float gather_mean32(const int* __restrict__ col, int d,
                                               const float* __restrict__ base, int stride,
                                               int lane) {
    float acc = 0.f;
    for (int e = 0; e < d; e += 8) {
        int idx[8];
        float v[8];
#pragma unroll
        for (int j = 0; j < 8; ++j) idx[j] = (e + j < d) ? __ldg(col + e + j) : -1;
#pragma unroll
        for (int j = 0; j < 8; ++j) v[j] = (idx[j] >= 0) ? __ldg(base + idx[j] * stride + lane) : 0.f;
        acc += ((v[0] + v[1]) + (v[2] + v[3])) + ((v[4] + v[5]) + (v[6] + v[7]));
    }
    return acc / fmaxf((float)d, 1.f);
}

__global__ void __launch_bounds__(256) k_pa() {
    int lane = threadIdx.x & 31;
    if (blockIdx.x < PA_BLKS_P) {
        int w = blockIdx.x * 8 + (threadIdx.x >> 5);
        int s  = __ldg(&g_rp[w]);      int d  = __ldg(&g_deg[w]);
        int s2 = __ldg(&g_rp[NP + w]); int d2 = __ldg(&g_deg[NP + w]);

        float mc = gather_mean32(g_col + s, d, g_P, 96, lane);
        float mw = gather_mean32(g_col + EE + s2, d2, g_A, 64, lane);

        float p = mc + mw + __ldg(g_P + (size_t)w * 96 + 64 + lane) + g_b1[lane];
        p = fmaxf(p, 0.f);
        float zc = p * g_uc[lane];
        float zr = p * g_wr2[lane];
#pragma unroll
        for (int o = 16; o; o >>= 1) {
            zc += __shfl_xor_sync(0xFFFFFFFFu, zc, o);
            zr += __shfl_xor_sync(0xFFFFFFFFu, zr, o);
        }
        if (lane == 0) { g_zc[w] = zc; g_zr[w] = zr; }
    } else {
        int w = (blockIdx.x - PA_BLKS_P) * 8 + (threadIdx.x >> 5);
        int s = __ldg(&g_rp[2 * NP + w]); int d = __ldg(&g_deg[2 * NP + w]);
        float mr = gather_mean32(g_col + 2 * EE + s, d, g_P + 32, 96, lane);

        float a1 = mr + __ldg(g_A + (size_t)w * 64 + 32 + lane) + g_brev[lane];
        a1 = fmaxf(a1, 0.f);
        float zw = a1 * g_uw[lane];
#pragma unroll
        for (int o = 16; o; o >>= 1) zw += __shfl_xor_sync(0xFFFFFFFFu, zw, o);
        if (lane == 0) g_zw[w] = zw;
    }
}

// ---------------- layer 2 scalar aggregation + head (MLP=8) ----------------
__device__ __forceinline__ float gather_mean1(const int* __restrict__ col, int d,
                                              const float* __restrict__ z) {
    float acc = 0.f;
    for (int e = 0; e < d; e += 8) {
        int idx[8];
        float v[8];
#pragma unroll
        for (int j = 0; j < 8; ++j) idx[j] = (e + j < d) ? __ldg(col + e + j) : -1;
#pragma unroll
        for (int j = 0; j < 8; ++j) v[j] = (idx[j] >= 0) ? __ldg(z + idx[j]) : 0.f;
        acc += ((v[0] + v[1]) + (v[2] + v[3])) + ((v[4] + v[5]) + (v[6] + v[7]));
    }
    return acc / fmaxf((float)d, 1.f);
}

__global__ void __launch_bounds__(256) k_out(float* __restrict__ out) {
    int i = blockIdx.x * blockDim.x + threadIdx.x;
    if (i >= NP) return;
    int s  = __ldg(&g_rp[i]);      int d  = __ldg(&g_deg[i]);
    int s2 = __ldg(&g_rp[NP + i]); int d2 = __ldg(&g_deg[NP + i]);
    float sc = gather_mean1(g_col + s, d, g_zc);
    float sw = gather_mean1(g_col + EE + s2, d2, g_zw);
    out[i] = sc + sw + __ldg(&g_zr[i]) + g_cbias;
}

// ---------------- launch ----------------
extern "C" void kernel_launch(void* const* d_in, const int* in_sizes, int n_in,
                              void* d_out, int out_size) {
    const float* x_paper  = (const float*)d_in[0];
    const float* x_author = (const float*)d_in[1];
    const int*   ei_c     = (const int*)d_in[2];
    const int*   ei_w     = (const int*)d_in[3];
    const int*   ei_r     = (const int*)d_in[4];
    float* out = (float*)d_out;

    k_init<<<ZERO_BLKS + 48, 256>>>(
        (const float*)d_in[5],  (const float*)d_in[6],  (const float*)d_in[7],
        (const float*)d_in[8],  (const float*)d_in[9],  (const float*)d_in[10],
        (const float*)d_in[11], (const float*)d_in[12], (const float*)d_in[13],
        (const float*)d_in[14], (const float*)d_in[15], (const float*)d_in[16],
        (const float*)d_in[17], (const float*)d_in[18], (const float*)d_in[19],
        (const float*)d_in[23], (const float*)d_in[24]);                       // 0
    k_hist3<<<(3 * EE + 255) / 256, 256>>>(ei_c + EE, ei_w + EE, ei_r + EE);   // 1
    k_alloc3<<<490, 256>>>();                                                  // 2
    k_gemm_all<<<GEMM_BLKS_P + GEMM_BLKS_A, 256>>>(x_paper, x_author);         // 3 (profiled slot)
    k_fill3<<<(3 * EE + 255) / 256, 256>>>(ei_c, ei_c + EE, ei_w, ei_w + EE, ei_r, ei_r + EE); // 4
    k_pa<<<PA_BLKS_P + PA_BLKS_A, 256>>>();                                    // 5
    k_out<<<(NP + 255) / 256, 256>>>(out);                                     // 6
}